// round 4
// baseline (speedup 1.0000x reference)
#include <cuda_runtime.h>
#include <math.h>

#define T_TOK  8192
#define D_IN   1024
#define D_HID  4096
#define NE     8
#define TOPK   2

#define BM 64
#define BN 64
#define BK 16
#define PADM   (T_TOK*TOPK + NE*BM)   /* 16896: worst-case padded rows */
#define MTILES (PADM/BM)              /* 264 */

// ---------------- scratch (static device globals; no allocation) ----------
__device__ __align__(16) float g_hid [(size_t)PADM * D_HID];  // ~277 MB
__device__ __align__(16) float g_out2[(size_t)PADM * D_IN];   // ~69 MB
__device__ int   g_sel[T_TOK*TOPK];
__device__ float g_wt [T_TOK*TOPK];
__device__ float g_prob_sum[NE];
__device__ int   g_count[NE];
__device__ int   g_fill[NE];
__device__ int   g_poff[NE+1];
__device__ int   g_ptot;
__device__ int   g_ptok[PADM];
__device__ int   g_t2p[T_TOK*TOPK];

// ---------------- init ----------------------------------------------------
__global__ void init_k() {
    int i = blockIdx.x * blockDim.x + threadIdx.x;
    if (i < PADM) g_ptok[i] = -1;
    if (i < NE) { g_prob_sum[i] = 0.f; g_count[i] = 0; g_fill[i] = 0; }
}

// ---------------- router: 1 warp per token --------------------------------
__global__ void router_k(const float* __restrict__ x, const float* __restrict__ gw) {
    __shared__ float sg[D_IN * NE];   // 32 KB gate weights
    __shared__ float s_prob[NE];
    __shared__ int   s_cnt[NE];
    int tid = threadIdx.x;
    for (int i = tid; i < D_IN * NE; i += 256) sg[i] = gw[i];
    if (tid < NE) { s_prob[tid] = 0.f; s_cnt[tid] = 0; }
    __syncthreads();

    int warp = tid >> 5, lane = tid & 31;
    int t = blockIdx.x * 8 + warp;
    const float* xr = x + (size_t)t * D_IN;

    float acc[NE];
#pragma unroll
    for (int e = 0; e < NE; e++) acc[e] = 0.f;
    for (int i = lane; i < D_IN; i += 32) {
        float xv = xr[i];
        const float* g = &sg[i * NE];
#pragma unroll
        for (int e = 0; e < NE; e++) acc[e] += xv * g[e];
    }
#pragma unroll
    for (int e = 0; e < NE; e++)
        for (int o = 16; o; o >>= 1) acc[e] += __shfl_xor_sync(0xffffffffu, acc[e], o);

    if (lane == 0) {
        float mx = acc[0];
#pragma unroll
        for (int e = 1; e < NE; e++) mx = fmaxf(mx, acc[e]);
        float p[NE], s = 0.f;
#pragma unroll
        for (int e = 0; e < NE; e++) { p[e] = expf(acc[e] - mx); s += p[e]; }
        float inv = 1.f / s;
#pragma unroll
        for (int e = 0; e < NE; e++) p[e] *= inv;

        // top-2, ties -> lower index (strict >)
        int i1 = 0;
#pragma unroll
        for (int e = 1; e < NE; e++) if (p[e] > p[i1]) i1 = e;
        int i2 = (i1 == 0) ? 1 : 0;
#pragma unroll
        for (int e = 0; e < NE; e++) if (e != i1 && p[e] > p[i2]) i2 = e;

        float d = p[i1] + p[i2] + 1e-6f;
        g_sel[t*2]   = i1;  g_sel[t*2+1] = i2;
        g_wt [t*2]   = p[i1] / d;
        g_wt [t*2+1] = p[i2] / d;
#pragma unroll
        for (int e = 0; e < NE; e++) atomicAdd(&s_prob[e], p[e]);
        atomicAdd(&s_cnt[i1], 1);
        atomicAdd(&s_cnt[i2], 1);
    }
    __syncthreads();
    if (tid < NE) {
        atomicAdd(&g_prob_sum[tid], s_prob[tid]);
        atomicAdd(&g_count[tid], s_cnt[tid]);
    }
}

// ---------------- offsets (tiny) ------------------------------------------
__global__ void offs_k() {
    int off = 0;
    for (int e = 0; e < NE; e++) {
        g_poff[e] = off;
        off += ((g_count[e] + BM - 1) / BM) * BM;
    }
    g_poff[NE] = off;
    g_ptot = off;
}

// ---------------- scatter --------------------------------------------------
__global__ void scat_k() {
    int t = blockIdx.x * blockDim.x + threadIdx.x;
    if (t >= T_TOK) return;
#pragma unroll
    for (int k = 0; k < TOPK; k++) {
        int e = g_sel[t*2 + k];
        int j = atomicAdd(&g_fill[e], 1);
        int pos = g_poff[e] + j;
        g_ptok[pos] = t;
        g_t2p[t*2 + k] = pos;
    }
}

// ---------------- GEMM1 + GELU:  H = gelu(Xg @ W1[e] + b1[e]) --------------
__device__ __forceinline__ float gelu_exact(float v) {
    return 0.5f * v * (1.0f + erff(v * 0.70710678118654752440f));
}

__global__ void __launch_bounds__(256) gemm1_k(const float* __restrict__ x,
                                               const float* __restrict__ W1,
                                               const float* __restrict__ b1) {
    __shared__ __align__(16) float As[BK][BM];
    __shared__ __align__(16) float Bs[BK][BN];
    __shared__ int s_tok[BM];

    int row0 = blockIdx.y * BM;
    if (row0 >= g_ptot) return;
    int e = 0;
    while (row0 >= g_poff[e + 1]) e++;

    int tid = threadIdx.x;
    if (tid < BM) s_tok[tid] = g_ptok[row0 + tid];
    __syncthreads();

    int n0 = blockIdx.x * BN;
    const float* Bp = W1 + (size_t)e * D_IN * D_HID + n0;

    int ar = tid >> 2, ak = (tid & 3) * 4;
    int bk = tid >> 4, bn = (tid & 15) * 4;
    int atok = s_tok[ar];
    const float* Ap = (atok >= 0) ? (x + (size_t)atok * D_IN + ak) : 0;

    float acc[4][4] = {};
    int ty = tid >> 4, tx = tid & 15;

    for (int k0 = 0; k0 < D_IN; k0 += BK) {
        float4 av = Ap ? *(const float4*)(Ap + k0) : make_float4(0.f, 0.f, 0.f, 0.f);
        As[ak + 0][ar] = av.x; As[ak + 1][ar] = av.y;
        As[ak + 2][ar] = av.z; As[ak + 3][ar] = av.w;
        float4 bv = *(const float4*)(Bp + (size_t)(k0 + bk) * D_HID + bn);
        *(float4*)&Bs[bk][bn] = bv;
        __syncthreads();
#pragma unroll
        for (int kk = 0; kk < BK; kk++) {
            float4 a = *(const float4*)&As[kk][ty * 4];
            float4 b = *(const float4*)&Bs[kk][tx * 4];
            acc[0][0] += a.x*b.x; acc[0][1] += a.x*b.y; acc[0][2] += a.x*b.z; acc[0][3] += a.x*b.w;
            acc[1][0] += a.y*b.x; acc[1][1] += a.y*b.y; acc[1][2] += a.y*b.z; acc[1][3] += a.y*b.w;
            acc[2][0] += a.z*b.x; acc[2][1] += a.z*b.y; acc[2][2] += a.z*b.z; acc[2][3] += a.z*b.w;
            acc[3][0] += a.w*b.x; acc[3][1] += a.w*b.y; acc[3][2] += a.w*b.z; acc[3][3] += a.w*b.w;
        }
        __syncthreads();
    }

#pragma unroll
    for (int i = 0; i < 4; i++) {
        int m = ty * 4 + i;
        if (s_tok[m] < 0) continue;
        float* hrow = &g_hid[(size_t)(row0 + m) * D_HID];
#pragma unroll
        for (int j = 0; j < 4; j++) {
            int n = n0 + tx * 4 + j;
            float v = acc[i][j] + b1[e * D_HID + n];
            hrow[n] = gelu_exact(v);
        }
    }
}

// ---------------- GEMM2 + bias:  S = H @ W2[e] + b2[e] ---------------------
__global__ void __launch_bounds__(256) gemm2_k(const float* __restrict__ W2,
                                               const float* __restrict__ b2) {
    __shared__ __align__(16) float As[BK][BM];
    __shared__ __align__(16) float Bs[BK][BN];

    int row0 = blockIdx.y * BM;
    if (row0 >= g_ptot) return;
    int e = 0;
    while (row0 >= g_poff[e + 1]) e++;

    int tid = threadIdx.x;
    int n0 = blockIdx.x * BN;
    const float* Bp = W2 + (size_t)e * D_HID * D_IN + n0;

    int ar = tid >> 2, ak = (tid & 3) * 4;
    int bk = tid >> 4, bn = (tid & 15) * 4;
    const float* Ap = &g_hid[(size_t)(row0 + ar) * D_HID + ak];

    float acc[4][4] = {};
    int ty = tid >> 4, tx = tid & 15;

    for (int k0 = 0; k0 < D_HID; k0 += BK) {
        float4 av = *(const float4*)(Ap + k0);
        As[ak + 0][ar] = av.x; As[ak + 1][ar] = av.y;
        As[ak + 2][ar] = av.z; As[ak + 3][ar] = av.w;
        float4 bv = *(const float4*)(Bp + (size_t)(k0 + bk) * D_IN + bn);
        *(float4*)&Bs[bk][bn] = bv;
        __syncthreads();
#pragma unroll
        for (int kk = 0; kk < BK; kk++) {
            float4 a = *(const float4*)&As[kk][ty * 4];
            float4 b = *(const float4*)&Bs[kk][tx * 4];
            acc[0][0] += a.x*b.x; acc[0][1] += a.x*b.y; acc[0][2] += a.x*b.z; acc[0][3] += a.x*b.w;
            acc[1][0] += a.y*b.x; acc[1][1] += a.y*b.y; acc[1][2] += a.y*b.z; acc[1][3] += a.y*b.w;
            acc[2][0] += a.z*b.x; acc[2][1] += a.z*b.y; acc[2][2] += a.z*b.z; acc[2][3] += a.z*b.w;
            acc[3][0] += a.w*b.x; acc[3][1] += a.w*b.y; acc[3][2] += a.w*b.z; acc[3][3] += a.w*b.w;
        }
        __syncthreads();
    }

#pragma unroll
    for (int i = 0; i < 4; i++) {
        int m = ty * 4 + i;
        float* srow = &g_out2[(size_t)(row0 + m) * D_IN];
#pragma unroll
        for (int j = 0; j < 4; j++) {
            int n = n0 + tx * 4 + j;
            srow[n] = acc[i][j] + b2[e * D_IN + n];
        }
    }
}

// ---------------- combine: out[t] = w0*S[p0] + w1*S[p1] --------------------
__global__ void comb_k(float* __restrict__ out) {
    int t = blockIdx.x;
    int c = threadIdx.x * 4;
    int p0 = g_t2p[t*2], p1 = g_t2p[t*2 + 1];
    float w0 = g_wt[t*2], w1 = g_wt[t*2 + 1];
    float4 a = *(const float4*)&g_out2[(size_t)p0 * D_IN + c];
    float4 b = *(const float4*)&g_out2[(size_t)p1 * D_IN + c];
    float4 o;
    o.x = w0 * a.x + w1 * b.x;
    o.y = w0 * a.y + w1 * b.y;
    o.z = w0 * a.z + w1 * b.z;
    o.w = w0 * a.w + w1 * b.w;
    *(float4*)&out[(size_t)t * D_IN + c] = o;
}

// ---------------- aux loss -------------------------------------------------
__global__ void aux_k(float* __restrict__ out, int out_size) {
    if (out_size <= T_TOK * D_IN) return;
    float s = 0.f;
    for (int e = 0; e < NE; e++) {
        float mean_prob = g_prob_sum[e] / (float)T_TOK;
        float frac = (float)g_count[e] / (float)(T_TOK * TOPK);
        s += mean_prob * frac;
    }
    out[T_TOK * D_IN] = (float)NE * s;
}

// ---------------- launch ---------------------------------------------------
extern "C" void kernel_launch(void* const* d_in, const int* in_sizes, int n_in,
                              void* d_out, int out_size) {
    const float* x   = (const float*)d_in[0];
    const float* gw  = (const float*)d_in[1];
    const float* W1  = (const float*)d_in[2];
    const float* b1  = (const float*)d_in[3];
    const float* W2  = (const float*)d_in[4];
    const float* b2  = (const float*)d_in[5];
    float* out = (float*)d_out;

    init_k  <<<(PADM + 255) / 256, 256>>>();
    router_k<<<T_TOK / 8, 256>>>(x, gw);
    offs_k  <<<1, 1>>>();
    scat_k  <<<T_TOK / 256, 256>>>();
    gemm1_k <<<dim3(D_HID / BN, MTILES), 256>>>(x, W1, b1);
    gemm2_k <<<dim3(D_IN / BN, MTILES), 256>>>(W2, b2);
    comb_k  <<<T_TOK, 256>>>(out);
    aux_k   <<<1, 1>>>(out, out_size);
}

// round 5
// speedup vs baseline: 4.7602x; 4.7602x over previous
#include <cuda_runtime.h>
#include <cuda_bf16.h>
#include <math.h>
#include <stdint.h>

#define T_TOK  8192
#define D_IN   1024
#define D_HID  4096
#define NE     8
#define TOPK   2

#define BM 128
#define BN 128
#define BK 32
#define PADM   (T_TOK*TOPK + NE*BM)   /* 17408 */
#define MTILES (PADM/BM)              /* 136 */

#define APAD 40    /* halfs per A smem row (32 data + 8 pad) */
#define BPAD 136   /* halfs per B smem row (128 data + 8 pad) */
#define AH_OFF 0
#define AL_OFF (BM*APAD)
#define BH_OFF (2*BM*APAD)
#define BL_OFF (2*BM*APAD + BK*BPAD)
#define ST_H   (2*BM*APAD + 2*BK*BPAD)   /* halfs per stage = 18944 */
#define SMEM_BYTES (2*ST_H*2)            /* 75776 B */

typedef __nv_bfloat16  bf16;
typedef __nv_bfloat162 bf162;

// ---------------- scratch (static device globals; no allocation) ----------
__device__ __align__(16) bf16 g_xh [(size_t)T_TOK*D_IN];
__device__ __align__(16) bf16 g_xl [(size_t)T_TOK*D_IN];
__device__ __align__(16) bf16 g_w1h[(size_t)NE*D_IN*D_HID];
__device__ __align__(16) bf16 g_w1l[(size_t)NE*D_IN*D_HID];
__device__ __align__(16) bf16 g_w2h[(size_t)NE*D_HID*D_IN];
__device__ __align__(16) bf16 g_w2l[(size_t)NE*D_HID*D_IN];
__device__ __align__(16) bf16 g_hh [(size_t)PADM*D_HID];
__device__ __align__(16) bf16 g_hl [(size_t)PADM*D_HID];
__device__ __align__(16) float g_out2[(size_t)PADM*D_IN];
__device__ int   g_sel[T_TOK*TOPK];
__device__ float g_wt [T_TOK*TOPK];
__device__ float g_prob_sum[NE];
__device__ int   g_count[NE];
__device__ int   g_fill[NE];
__device__ int   g_poff[NE+1];
__device__ int   g_ptot;
__device__ int   g_ptok[PADM];
__device__ int   g_t2p[T_TOK*TOPK];

// ---------------- fp32 -> bf16 hi/lo split ---------------------------------
__global__ void split_k(const float4* __restrict__ in, bf162* __restrict__ h,
                        bf162* __restrict__ l, int n4) {
    int i = blockIdx.x * blockDim.x + threadIdx.x;
    if (i >= n4) return;
    float4 v = in[i];
    bf16 h0 = __float2bfloat16(v.x), h1 = __float2bfloat16(v.y);
    bf16 h2 = __float2bfloat16(v.z), h3 = __float2bfloat16(v.w);
    bf16 l0 = __float2bfloat16(v.x - __bfloat162float(h0));
    bf16 l1 = __float2bfloat16(v.y - __bfloat162float(h1));
    bf16 l2 = __float2bfloat16(v.z - __bfloat162float(h2));
    bf16 l3 = __float2bfloat16(v.w - __bfloat162float(h3));
    bf162 a; a.x = h0; a.y = h1;
    bf162 b; b.x = h2; b.y = h3;
    h[2*i] = a; h[2*i+1] = b;
    a.x = l0; a.y = l1; b.x = l2; b.y = l3;
    l[2*i] = a; l[2*i+1] = b;
}

// ---------------- init ----------------------------------------------------
__global__ void init_k() {
    int i = blockIdx.x * blockDim.x + threadIdx.x;
    if (i < PADM) g_ptok[i] = -1;
    if (i < NE) { g_prob_sum[i] = 0.f; g_count[i] = 0; g_fill[i] = 0; }
}

// ---------------- router: 1 warp per token --------------------------------
__global__ void router_k(const float* __restrict__ x, const float* __restrict__ gw) {
    __shared__ float sg[D_IN * NE];
    __shared__ float s_prob[NE];
    __shared__ int   s_cnt[NE];
    int tid = threadIdx.x;
    for (int i = tid; i < D_IN * NE; i += 256) sg[i] = gw[i];
    if (tid < NE) { s_prob[tid] = 0.f; s_cnt[tid] = 0; }
    __syncthreads();

    int warp = tid >> 5, lane = tid & 31;
    int t = blockIdx.x * 8 + warp;
    const float* xr = x + (size_t)t * D_IN;

    float acc[NE];
#pragma unroll
    for (int e = 0; e < NE; e++) acc[e] = 0.f;
    for (int i = lane; i < D_IN; i += 32) {
        float xv = xr[i];
        const float* g = &sg[i * NE];
#pragma unroll
        for (int e = 0; e < NE; e++) acc[e] += xv * g[e];
    }
#pragma unroll
    for (int e = 0; e < NE; e++)
        for (int o = 16; o; o >>= 1) acc[e] += __shfl_xor_sync(0xffffffffu, acc[e], o);

    if (lane == 0) {
        float mx = acc[0];
#pragma unroll
        for (int e = 1; e < NE; e++) mx = fmaxf(mx, acc[e]);
        float p[NE], s = 0.f;
#pragma unroll
        for (int e = 0; e < NE; e++) { p[e] = expf(acc[e] - mx); s += p[e]; }
        float inv = 1.f / s;
#pragma unroll
        for (int e = 0; e < NE; e++) p[e] *= inv;

        int i1 = 0;
#pragma unroll
        for (int e = 1; e < NE; e++) if (p[e] > p[i1]) i1 = e;
        int i2 = (i1 == 0) ? 1 : 0;
#pragma unroll
        for (int e = 0; e < NE; e++) if (e != i1 && p[e] > p[i2]) i2 = e;

        float d = p[i1] + p[i2] + 1e-6f;
        g_sel[t*2]   = i1;  g_sel[t*2+1] = i2;
        g_wt [t*2]   = p[i1] / d;
        g_wt [t*2+1] = p[i2] / d;
#pragma unroll
        for (int e = 0; e < NE; e++) atomicAdd(&s_prob[e], p[e]);
        atomicAdd(&s_cnt[i1], 1);
        atomicAdd(&s_cnt[i2], 1);
    }
    __syncthreads();
    if (tid < NE) {
        atomicAdd(&g_prob_sum[tid], s_prob[tid]);
        atomicAdd(&g_count[tid], s_cnt[tid]);
    }
}

// ---------------- offsets (tiny) ------------------------------------------
__global__ void offs_k() {
    int off = 0;
    for (int e = 0; e < NE; e++) {
        g_poff[e] = off;
        off += ((g_count[e] + BM - 1) / BM) * BM;
    }
    g_poff[NE] = off;
    g_ptot = off;
}

// ---------------- scatter --------------------------------------------------
__global__ void scat_k() {
    int t = blockIdx.x * blockDim.x + threadIdx.x;
    if (t >= T_TOK) return;
#pragma unroll
    for (int k = 0; k < TOPK; k++) {
        int e = g_sel[t*2 + k];
        int j = atomicAdd(&g_fill[e], 1);
        int pos = g_poff[e] + j;
        g_ptok[pos] = t;
        g_t2p[t*2 + k] = pos;
    }
}

// ---------------- MMA helpers ----------------------------------------------
__device__ __forceinline__ void cpa16(uint32_t dst, const void* src) {
    asm volatile("cp.async.cg.shared.global [%0], [%1], 16;\n" :: "r"(dst), "l"(src));
}
__device__ __forceinline__ void ldmx4(uint32_t* r, uint32_t addr) {
    asm volatile("ldmatrix.sync.aligned.m8n8.x4.shared.b16 {%0,%1,%2,%3}, [%4];\n"
        : "=r"(r[0]), "=r"(r[1]), "=r"(r[2]), "=r"(r[3]) : "r"(addr));
}
__device__ __forceinline__ void ldmx4t(uint32_t* r, uint32_t addr) {
    asm volatile("ldmatrix.sync.aligned.m8n8.x4.trans.shared.b16 {%0,%1,%2,%3}, [%4];\n"
        : "=r"(r[0]), "=r"(r[1]), "=r"(r[2]), "=r"(r[3]) : "r"(addr));
}
__device__ __forceinline__ void mma16816(float* c, const uint32_t* a, const uint32_t* b) {
    asm volatile("mma.sync.aligned.m16n8k16.row.col.f32.bf16.bf16.f32 "
        "{%0,%1,%2,%3}, {%4,%5,%6,%7}, {%8,%9}, {%0,%1,%2,%3};\n"
        : "+f"(c[0]), "+f"(c[1]), "+f"(c[2]), "+f"(c[3])
        : "r"(a[0]), "r"(a[1]), "r"(a[2]), "r"(a[3]), "r"(b[0]), "r"(b[1]));
}
__device__ __forceinline__ float gelu_exact(float v) {
    return 0.5f * v * (1.0f + erff(v * 0.70710678118654752440f));
}

// ---------------- split-precision MMA GEMM ---------------------------------
template<int KD, int ND, bool GATHER, bool GELU>
__global__ void __launch_bounds__(256, 1) gemm_mma(
    const bf16* __restrict__ Ah_g, const bf16* __restrict__ Al_g,
    const bf16* __restrict__ Bh_g, const bf16* __restrict__ Bl_g,
    const float* __restrict__ bias)
{
    extern __shared__ bf16 smem[];
    __shared__ int s_tok[BM];

    int row0 = blockIdx.y * BM;
    if (row0 >= g_ptot) return;
    int e = 0;
    while (row0 >= g_poff[e + 1]) e++;
    int n0 = blockIdx.x * BN;

    int tid = threadIdx.x;
    if (GATHER) {
        if (tid < BM) { int t = g_ptok[row0 + tid]; s_tok[tid] = (t < 0) ? 0 : t; }
        __syncthreads();
    }

    const bf16* Bh_e = Bh_g + (size_t)e * KD * ND + n0;
    const bf16* Bl_e = Bl_g + (size_t)e * KD * ND + n0;

    uint32_t smem_base = (uint32_t)__cvta_generic_to_shared(smem);

    auto load_stage = [&](int stage, int k0) {
        uint32_t sb = smem_base + stage * (ST_H * 2);
#pragma unroll
        for (int m = 0; m < 2; m++) {
            int c = tid + m * 256;              // 0..511
            int r = c >> 2, j = c & 3;          // A: 128 rows x 4 chunks(16B)
            size_t arow = GATHER ? (size_t)s_tok[r] * KD : (size_t)(row0 + r) * KD;
            uint32_t offA = (uint32_t)(r * APAD + j * 8) * 2;
            cpa16(sb + AH_OFF * 2 + offA, Ah_g + arow + k0 + j * 8);
            cpa16(sb + AL_OFF * 2 + offA, Al_g + arow + k0 + j * 8);
            int rb = c >> 4, jb = c & 15;       // B: 32 rows x 16 chunks(16B)
            size_t brow = (size_t)(k0 + rb) * ND + jb * 8;
            uint32_t offB = (uint32_t)(rb * BPAD + jb * 8) * 2;
            cpa16(sb + BH_OFF * 2 + offB, Bh_e + brow);
            cpa16(sb + BL_OFF * 2 + offB, Bl_e + brow);
        }
    };

    int lane = tid & 31, warp = tid >> 5;
    int wm = (warp >> 2) * 64;
    int wn = (warp & 3) * 32;
    uint32_t rowSel = (lane & 7) + ((lane >> 3) & 1) * 8;
    uint32_t colSel = (lane >> 4) * 8;

    float acc[4][4][4];
#pragma unroll
    for (int i = 0; i < 4; i++)
#pragma unroll
        for (int j = 0; j < 4; j++)
#pragma unroll
            for (int q = 0; q < 4; q++) acc[i][j][q] = 0.f;

    auto compute = [&](int stage) {
        uint32_t sb = smem_base + stage * (ST_H * 2);
        uint32_t ah = sb + AH_OFF * 2, al = sb + AL_OFF * 2;
        uint32_t bh = sb + BH_OFF * 2, bl = sb + BL_OFF * 2;
#pragma unroll
        for (int kk = 0; kk < 2; kk++) {
            int k16 = kk * 16;
            uint32_t bhF[2][4], blF[2][4];
#pragma unroll
            for (int nj = 0; nj < 2; nj++) {
                uint32_t off = (uint32_t)((k16 + rowSel) * BPAD + wn + nj * 16 + colSel) * 2;
                ldmx4t(bhF[nj], bh + off);
                ldmx4t(blF[nj], bl + off);
            }
            uint32_t aF[4][4];
#pragma unroll
            for (int mi = 0; mi < 4; mi++) {
                uint32_t off = (uint32_t)((wm + mi * 16 + rowSel) * APAD + k16 + colSel) * 2;
                ldmx4(aF[mi], ah + off);
            }
#pragma unroll
            for (int mi = 0; mi < 4; mi++)
#pragma unroll
                for (int ni = 0; ni < 4; ni++) {
                    mma16816(acc[mi][ni], aF[mi], &bhF[ni >> 1][(ni & 1) * 2]);
                    mma16816(acc[mi][ni], aF[mi], &blF[ni >> 1][(ni & 1) * 2]);
                }
#pragma unroll
            for (int mi = 0; mi < 4; mi++) {
                uint32_t off = (uint32_t)((wm + mi * 16 + rowSel) * APAD + k16 + colSel) * 2;
                ldmx4(aF[mi], al + off);
            }
#pragma unroll
            for (int mi = 0; mi < 4; mi++)
#pragma unroll
                for (int ni = 0; ni < 4; ni++)
                    mma16816(acc[mi][ni], aF[mi], &bhF[ni >> 1][(ni & 1) * 2]);
        }
    };

    const int NIT = KD / BK;
    load_stage(0, 0);
    asm volatile("cp.async.commit_group;\n");
    int stage = 0;
#pragma unroll 1
    for (int it = 0; it < NIT; ++it) {
        if (it + 1 < NIT) {
            load_stage(stage ^ 1, (it + 1) * BK);
            asm volatile("cp.async.commit_group;\n");
            asm volatile("cp.async.wait_group 1;\n");
        } else {
            asm volatile("cp.async.wait_group 0;\n");
        }
        __syncthreads();
        compute(stage);
        __syncthreads();
        stage ^= 1;
    }

    int g = lane >> 2, tg = lane & 3;
#pragma unroll
    for (int mi = 0; mi < 4; mi++)
#pragma unroll
        for (int ni = 0; ni < 4; ni++)
#pragma unroll
            for (int h = 0; h < 2; h++) {
                int m = wm + mi * 16 + g + h * 8;
                int n = n0 + wn + ni * 8 + 2 * tg;
                size_t orow = (size_t)(row0 + m) * ND + n;
                float v0 = acc[mi][ni][h * 2 + 0] + bias[e * ND + n];
                float v1 = acc[mi][ni][h * 2 + 1] + bias[e * ND + n + 1];
                if (GELU) {
                    v0 = gelu_exact(v0);
                    v1 = gelu_exact(v1);
                    bf16 h0 = __float2bfloat16(v0), h1 = __float2bfloat16(v1);
                    bf16 l0 = __float2bfloat16(v0 - __bfloat162float(h0));
                    bf16 l1 = __float2bfloat16(v1 - __bfloat162float(h1));
                    bf162 ph; ph.x = h0; ph.y = h1;
                    bf162 pl; pl.x = l0; pl.y = l1;
                    *(bf162*)&g_hh[orow] = ph;
                    *(bf162*)&g_hl[orow] = pl;
                } else {
                    *(float2*)&g_out2[orow] = make_float2(v0, v1);
                }
            }
}

// ---------------- combine --------------------------------------------------
__global__ void comb_k(float* __restrict__ out) {
    int t = blockIdx.x;
    int c = threadIdx.x * 4;
    int p0 = g_t2p[t*2], p1 = g_t2p[t*2 + 1];
    float w0 = g_wt[t*2], w1 = g_wt[t*2 + 1];
    float4 a = *(const float4*)&g_out2[(size_t)p0 * D_IN + c];
    float4 b = *(const float4*)&g_out2[(size_t)p1 * D_IN + c];
    float4 o;
    o.x = w0 * a.x + w1 * b.x;
    o.y = w0 * a.y + w1 * b.y;
    o.z = w0 * a.z + w1 * b.z;
    o.w = w0 * a.w + w1 * b.w;
    *(float4*)&out[(size_t)t * D_IN + c] = o;
}

// ---------------- aux loss -------------------------------------------------
__global__ void aux_k(float* __restrict__ out, int out_size) {
    if (out_size <= T_TOK * D_IN) return;
    float s = 0.f;
    for (int e = 0; e < NE; e++) {
        float mean_prob = g_prob_sum[e] / (float)T_TOK;
        float frac = (float)g_count[e] / (float)(T_TOK * TOPK);
        s += mean_prob * frac;
    }
    out[T_TOK * D_IN] = (float)NE * s;
}

// ---------------- launch ---------------------------------------------------
extern "C" void kernel_launch(void* const* d_in, const int* in_sizes, int n_in,
                              void* d_out, int out_size) {
    const float* x   = (const float*)d_in[0];
    const float* gw  = (const float*)d_in[1];
    const float* W1  = (const float*)d_in[2];
    const float* b1  = (const float*)d_in[3];
    const float* W2  = (const float*)d_in[4];
    const float* b2  = (const float*)d_in[5];
    float* out = (float*)d_out;

    cudaFuncSetAttribute(gemm_mma<D_IN, D_HID, true, true>,
                         cudaFuncAttributeMaxDynamicSharedMemorySize, SMEM_BYTES);
    cudaFuncSetAttribute(gemm_mma<D_HID, D_IN, false, false>,
                         cudaFuncAttributeMaxDynamicSharedMemorySize, SMEM_BYTES);

    bf16 *xh, *xl, *w1h, *w1l, *w2h, *w2l, *hh, *hl;
    cudaGetSymbolAddress((void**)&xh,  g_xh);
    cudaGetSymbolAddress((void**)&xl,  g_xl);
    cudaGetSymbolAddress((void**)&w1h, g_w1h);
    cudaGetSymbolAddress((void**)&w1l, g_w1l);
    cudaGetSymbolAddress((void**)&w2h, g_w2h);
    cudaGetSymbolAddress((void**)&w2l, g_w2l);
    cudaGetSymbolAddress((void**)&hh,  g_hh);
    cudaGetSymbolAddress((void**)&hl,  g_hl);

    int nx  = T_TOK * D_IN / 4;
    int nw1 = NE * D_IN * D_HID / 4;
    int nw2 = NE * D_HID * D_IN / 4;
    split_k<<<(nx  + 255) / 256, 256>>>((const float4*)x,  (bf162*)xh,  (bf162*)xl,  nx);
    split_k<<<(nw1 + 255) / 256, 256>>>((const float4*)W1, (bf162*)w1h, (bf162*)w1l, nw1);
    split_k<<<(nw2 + 255) / 256, 256>>>((const float4*)W2, (bf162*)w2h, (bf162*)w2l, nw2);

    init_k  <<<(PADM + 255) / 256, 256>>>();
    router_k<<<T_TOK / 8, 256>>>(x, gw);
    offs_k  <<<1, 1>>>();
    scat_k  <<<T_TOK / 256, 256>>>();

    gemm_mma<D_IN, D_HID, true, true>
        <<<dim3(D_HID / BN, MTILES), 256, SMEM_BYTES>>>(xh, xl, w1h, w1l, b1);
    gemm_mma<D_HID, D_IN, false, false>
        <<<dim3(D_IN / BN, MTILES), 256, SMEM_BYTES>>>(hh, hl, w2h, w2l, b2);

    comb_k  <<<T_TOK, 256>>>(out);
    aux_k   <<<1, 1>>>(out, out_size);
}

// round 8
// speedup vs baseline: 5.4261x; 1.1399x over previous
#include <cuda_runtime.h>
#include <cuda_bf16.h>
#include <math.h>
#include <stdint.h>

#define T_TOK  8192
#define D_IN   1024
#define D_HID  4096
#define NE     8
#define TOPK   2

#define BM 128
#define BN 128
#define BK 32
#define PADM   (T_TOK*TOPK + NE*BM)   /* 17408 */
#define MTILES (PADM/BM)              /* 136 */

#define APAD 40    /* halfs per A smem row (32 data + 8 pad) */
#define BPAD 136   /* halfs per B smem row (128 data + 8 pad) */
#define AH_OFF 0
#define AL_OFF (BM*APAD)
#define BH_OFF (2*BM*APAD)
#define BL_OFF (2*BM*APAD + BK*BPAD)
#define ST_H   (2*BM*APAD + 2*BK*BPAD)   /* halfs per stage = 18944 */
#define NSTG   4
#define SMEM_BYTES (NSTG*ST_H*2)         /* 151552 B */

typedef __nv_bfloat16  bf16;
typedef __nv_bfloat162 bf162;

// ---------------- scratch (static device globals; no allocation) ----------
__device__ __align__(16) bf16 g_xh [(size_t)T_TOK*D_IN];
__device__ __align__(16) bf16 g_xl [(size_t)T_TOK*D_IN];
__device__ __align__(16) bf16 g_w1h[(size_t)NE*D_IN*D_HID];
__device__ __align__(16) bf16 g_w1l[(size_t)NE*D_IN*D_HID];
__device__ __align__(16) bf16 g_w2h[(size_t)NE*D_HID*D_IN];
__device__ __align__(16) bf16 g_w2l[(size_t)NE*D_HID*D_IN];
__device__ __align__(16) bf16 g_hh [(size_t)PADM*D_HID];
__device__ __align__(16) bf16 g_hl [(size_t)PADM*D_HID];
__device__ int   g_sel[T_TOK*TOPK];
__device__ float g_wt [T_TOK*TOPK];
__device__ float g_wtp[PADM];
__device__ float g_prob_sum[NE];
__device__ int   g_count[NE];
__device__ int   g_fill[NE];
__device__ int   g_poff[NE+1];
__device__ int   g_ptot;
__device__ int   g_ptok[PADM];
__device__ int   g_t2p[T_TOK*TOPK];

// ---------------- fp32 -> bf16 hi/lo split ---------------------------------
__global__ void split_k(const float4* __restrict__ in, bf162* __restrict__ h,
                        bf162* __restrict__ l, int n4) {
    int i = blockIdx.x * blockDim.x + threadIdx.x;
    if (i >= n4) return;
    float4 v = in[i];
    bf16 h0 = __float2bfloat16(v.x), h1 = __float2bfloat16(v.y);
    bf16 h2 = __float2bfloat16(v.z), h3 = __float2bfloat16(v.w);
    bf16 l0 = __float2bfloat16(v.x - __bfloat162float(h0));
    bf16 l1 = __float2bfloat16(v.y - __bfloat162float(h1));
    bf16 l2 = __float2bfloat16(v.z - __bfloat162float(h2));
    bf16 l3 = __float2bfloat16(v.w - __bfloat162float(h3));
    bf162 a; a.x = h0; a.y = h1;
    bf162 b; b.x = h2; b.y = h3;
    h[2*i] = a; h[2*i+1] = b;
    a.x = l0; a.y = l1; b.x = l2; b.y = l3;
    l[2*i] = a; l[2*i+1] = b;
}

// ---------------- init: counters, ptok, and zero the output ----------------
__global__ void init_k(float4* __restrict__ out4) {
    int i = blockIdx.x * blockDim.x + threadIdx.x;
    if (i < T_TOK * D_IN / 4) out4[i] = make_float4(0.f, 0.f, 0.f, 0.f);
    if (i < PADM) g_ptok[i] = -1;
    if (i < NE) { g_prob_sum[i] = 0.f; g_count[i] = 0; g_fill[i] = 0; }
}

// ---------------- router: 1 warp per token --------------------------------
__global__ void router_k(const float* __restrict__ x, const float* __restrict__ gw) {
    __shared__ float sg[D_IN * NE];
    __shared__ float s_prob[NE];
    __shared__ int   s_cnt[NE];
    int tid = threadIdx.x;
    for (int i = tid; i < D_IN * NE; i += 256) sg[i] = gw[i];
    if (tid < NE) { s_prob[tid] = 0.f; s_cnt[tid] = 0; }
    __syncthreads();

    int warp = tid >> 5, lane = tid & 31;
    int t = blockIdx.x * 8 + warp;
    const float* xr = x + (size_t)t * D_IN;

    float acc[NE];
#pragma unroll
    for (int e = 0; e < NE; e++) acc[e] = 0.f;
    for (int i = lane; i < D_IN; i += 32) {
        float xv = xr[i];
        const float* g = &sg[i * NE];
#pragma unroll
        for (int e = 0; e < NE; e++) acc[e] += xv * g[e];
    }
#pragma unroll
    for (int e = 0; e < NE; e++)
        for (int o = 16; o; o >>= 1) acc[e] += __shfl_xor_sync(0xffffffffu, acc[e], o);

    if (lane == 0) {
        float mx = acc[0];
#pragma unroll
        for (int e = 1; e < NE; e++) mx = fmaxf(mx, acc[e]);
        float p[NE], s = 0.f;
#pragma unroll
        for (int e = 0; e < NE; e++) { p[e] = expf(acc[e] - mx); s += p[e]; }
        float inv = 1.f / s;
#pragma unroll
        for (int e = 0; e < NE; e++) p[e] *= inv;

        int i1 = 0;
#pragma unroll
        for (int e = 1; e < NE; e++) if (p[e] > p[i1]) i1 = e;
        int i2 = (i1 == 0) ? 1 : 0;
#pragma unroll
        for (int e = 0; e < NE; e++) if (e != i1 && p[e] > p[i2]) i2 = e;

        float d = p[i1] + p[i2] + 1e-6f;
        g_sel[t*2]   = i1;  g_sel[t*2+1] = i2;
        g_wt [t*2]   = p[i1] / d;
        g_wt [t*2+1] = p[i2] / d;
#pragma unroll
        for (int e = 0; e < NE; e++) atomicAdd(&s_prob[e], p[e]);
        atomicAdd(&s_cnt[i1], 1);
        atomicAdd(&s_cnt[i2], 1);
    }
    __syncthreads();
    if (tid < NE) {
        atomicAdd(&g_prob_sum[tid], s_prob[tid]);
        atomicAdd(&g_count[tid], s_cnt[tid]);
    }
}

// ---------------- offsets (tiny) ------------------------------------------
__global__ void offs_k() {
    int off = 0;
    for (int e = 0; e < NE; e++) {
        g_poff[e] = off;
        off += ((g_count[e] + BM - 1) / BM) * BM;
    }
    g_poff[NE] = off;
    g_ptot = off;
}

// ---------------- scatter --------------------------------------------------
__global__ void scat_k() {
    int t = blockIdx.x * blockDim.x + threadIdx.x;
    if (t >= T_TOK) return;
#pragma unroll
    for (int k = 0; k < TOPK; k++) {
        int e = g_sel[t*2 + k];
        int j = atomicAdd(&g_fill[e], 1);
        int pos = g_poff[e] + j;
        g_ptok[pos] = t;
        g_wtp[pos]  = g_wt[t*2 + k];
        g_t2p[t*2 + k] = pos;
    }
}

// ---------------- MMA helpers ----------------------------------------------
__device__ __forceinline__ void cpa16(uint32_t dst, const void* src) {
    asm volatile("cp.async.cg.shared.global [%0], [%1], 16;\n" :: "r"(dst), "l"(src));
}
__device__ __forceinline__ void ldmx4(uint32_t* r, uint32_t addr) {
    asm volatile("ldmatrix.sync.aligned.m8n8.x4.shared.b16 {%0,%1,%2,%3}, [%4];\n"
        : "=r"(r[0]), "=r"(r[1]), "=r"(r[2]), "=r"(r[3]) : "r"(addr));
}
__device__ __forceinline__ void ldmx4t(uint32_t* r, uint32_t addr) {
    asm volatile("ldmatrix.sync.aligned.m8n8.x4.trans.shared.b16 {%0,%1,%2,%3}, [%4];\n"
        : "=r"(r[0]), "=r"(r[1]), "=r"(r[2]), "=r"(r[3]) : "r"(addr));
}
__device__ __forceinline__ void mma16816(float* c, const uint32_t* a, const uint32_t* b) {
    asm volatile("mma.sync.aligned.m16n8k16.row.col.f32.bf16.bf16.f32 "
        "{%0,%1,%2,%3}, {%4,%5,%6,%7}, {%8,%9}, {%0,%1,%2,%3};\n"
        : "+f"(c[0]), "+f"(c[1]), "+f"(c[2]), "+f"(c[3])
        : "r"(a[0]), "r"(a[1]), "r"(a[2]), "r"(a[3]), "r"(b[0]), "r"(b[1]));
}
__device__ __forceinline__ float gelu_exact(float v) {
    return 0.5f * v * (1.0f + erff(v * 0.70710678118654752440f));
}

// ---------------- split-precision MMA GEMM ---------------------------------
// FIRST=true : A gathered by token, epilogue = bias+GELU -> hi/lo bf16 hidden
// FIRST=false: A = permuted hidden rows, epilogue = (acc+bias)*w atomicAdd out
template<int KD, int ND, bool FIRST>
__global__ void __launch_bounds__(256, 1) gemm_mma(
    const bf16* __restrict__ Ah_g, const bf16* __restrict__ Al_g,
    const bf16* __restrict__ Bh_g, const bf16* __restrict__ Bl_g,
    const float* __restrict__ bias, float* __restrict__ out)
{
    extern __shared__ bf16 smem[];
    __shared__ int   s_tok[BM];
    __shared__ float s_w[BM];

    int row0 = blockIdx.y * BM;
    if (row0 >= g_ptot) return;
    int e = 0;
    while (row0 >= g_poff[e + 1]) e++;
    int n0 = blockIdx.x * BN;

    int tid = threadIdx.x;
    if (tid < BM) {
        int t = g_ptok[row0 + tid];
        s_tok[tid] = t;
        if (!FIRST) s_w[tid] = g_wtp[row0 + tid];
    }
    __syncthreads();

    const bf16* Bh_e = Bh_g + (size_t)e * KD * ND + n0;
    const bf16* Bl_e = Bl_g + (size_t)e * KD * ND + n0;

    uint32_t smem_base = (uint32_t)__cvta_generic_to_shared(smem);

    auto load_stage = [&](int stage, int k0) {
        uint32_t sb = smem_base + (uint32_t)stage * (ST_H * 2);
#pragma unroll
        for (int m = 0; m < 2; m++) {
            int c = tid + m * 256;              // 0..511
            int r = c >> 2, j = c & 3;          // A: 128 rows x 4 chunks(16B)
            int tk = s_tok[r];
            size_t arow = FIRST ? (size_t)(tk < 0 ? 0 : tk) * KD : (size_t)(row0 + r) * KD;
            uint32_t offA = (uint32_t)(r * APAD + j * 8) * 2;
            cpa16(sb + AH_OFF * 2 + offA, Ah_g + arow + k0 + j * 8);
            cpa16(sb + AL_OFF * 2 + offA, Al_g + arow + k0 + j * 8);
            int rb = c >> 4, jb = c & 15;       // B: 32 rows x 16 chunks(16B)
            size_t brow = (size_t)(k0 + rb) * ND + jb * 8;
            uint32_t offB = (uint32_t)(rb * BPAD + jb * 8) * 2;
            cpa16(sb + BH_OFF * 2 + offB, Bh_e + brow);
            cpa16(sb + BL_OFF * 2 + offB, Bl_e + brow);
        }
    };

    int lane = tid & 31, warp = tid >> 5;
    int wm = (warp >> 2) * 64;
    int wn = (warp & 3) * 32;
    uint32_t rowSel = (lane & 7) + ((lane >> 3) & 1) * 8;
    uint32_t colSel = (lane >> 4) * 8;

    float acc[4][4][4];
#pragma unroll
    for (int i = 0; i < 4; i++)
#pragma unroll
        for (int j = 0; j < 4; j++)
#pragma unroll
            for (int q = 0; q < 4; q++) acc[i][j][q] = 0.f;

    auto compute = [&](int stage) {
        uint32_t sb = smem_base + (uint32_t)stage * (ST_H * 2);
        uint32_t ah = sb + AH_OFF * 2, al = sb + AL_OFF * 2;
        uint32_t bh = sb + BH_OFF * 2, bl = sb + BL_OFF * 2;
#pragma unroll
        for (int kk = 0; kk < 2; kk++) {
            int k16 = kk * 16;
            uint32_t bhF[2][4], blF[2][4];
#pragma unroll
            for (int nj = 0; nj < 2; nj++) {
                uint32_t off = (uint32_t)((k16 + rowSel) * BPAD + wn + nj * 16 + colSel) * 2;
                ldmx4t(bhF[nj], bh + off);
                ldmx4t(blF[nj], bl + off);
            }
            uint32_t aF[4][4];
#pragma unroll
            for (int mi = 0; mi < 4; mi++) {
                uint32_t off = (uint32_t)((wm + mi * 16 + rowSel) * APAD + k16 + colSel) * 2;
                ldmx4(aF[mi], ah + off);
            }
#pragma unroll
            for (int mi = 0; mi < 4; mi++)
#pragma unroll
                for (int ni = 0; ni < 4; ni++) {
                    mma16816(acc[mi][ni], aF[mi], &bhF[ni >> 1][(ni & 1) * 2]);
                    mma16816(acc[mi][ni], aF[mi], &blF[ni >> 1][(ni & 1) * 2]);
                }
#pragma unroll
            for (int mi = 0; mi < 4; mi++) {
                uint32_t off = (uint32_t)((wm + mi * 16 + rowSel) * APAD + k16 + colSel) * 2;
                ldmx4(aF[mi], al + off);
            }
#pragma unroll
            for (int mi = 0; mi < 4; mi++)
#pragma unroll
                for (int ni = 0; ni < 4; ni++)
                    mma16816(acc[mi][ni], aF[mi], &bhF[ni >> 1][(ni & 1) * 2]);
        }
    };

    const int NIT = KD / BK;
    // prologue: fill 3 of 4 stages
    load_stage(0, 0);
    asm volatile("cp.async.commit_group;\n");
    load_stage(1, BK);
    asm volatile("cp.async.commit_group;\n");
    load_stage(2, 2 * BK);
    asm volatile("cp.async.commit_group;\n");

#pragma unroll 1
    for (int it = 0; it < NIT; ++it) {
        asm volatile("cp.async.wait_group 2;\n");
        __syncthreads();
        compute(it & (NSTG - 1));
        if (it + 3 < NIT) load_stage((it + 3) & (NSTG - 1), (it + 3) * BK);
        asm volatile("cp.async.commit_group;\n");   // always: keeps group count uniform
    }

    int g = lane >> 2, tg = lane & 3;
#pragma unroll
    for (int mi = 0; mi < 4; mi++)
#pragma unroll
        for (int ni = 0; ni < 4; ni++)
#pragma unroll
            for (int h = 0; h < 2; h++) {
                int m = wm + mi * 16 + g + h * 8;
                int n = n0 + wn + ni * 8 + 2 * tg;
                float v0 = acc[mi][ni][h * 2 + 0] + bias[e * ND + n];
                float v1 = acc[mi][ni][h * 2 + 1] + bias[e * ND + n + 1];
                if (FIRST) {
                    if (s_tok[m] < 0) continue;
                    size_t orow = (size_t)(row0 + m) * ND + n;
                    v0 = gelu_exact(v0);
                    v1 = gelu_exact(v1);
                    bf16 h0 = __float2bfloat16(v0), h1 = __float2bfloat16(v1);
                    bf16 l0 = __float2bfloat16(v0 - __bfloat162float(h0));
                    bf16 l1 = __float2bfloat16(v1 - __bfloat162float(h1));
                    bf162 ph; ph.x = h0; ph.y = h1;
                    bf162 pl; pl.x = l0; pl.y = l1;
                    *(bf162*)&g_hh[orow] = ph;
                    *(bf162*)&g_hl[orow] = pl;
                } else {
                    int tok = s_tok[m];
                    if (tok < 0) continue;
                    float w = s_w[m];
                    atomicAdd(&out[(size_t)tok * ND + n],     v0 * w);
                    atomicAdd(&out[(size_t)tok * ND + n + 1], v1 * w);
                }
            }
}

// ---------------- aux loss -------------------------------------------------
__global__ void aux_k(float* __restrict__ out, int out_size) {
    if (out_size <= T_TOK * D_IN) return;
    float s = 0.f;
    for (int e = 0; e < NE; e++) {
        float mean_prob = g_prob_sum[e] / (float)T_TOK;
        float frac = (float)g_count[e] / (float)(T_TOK * TOPK);
        s += mean_prob * frac;
    }
    out[T_TOK * D_IN] = (float)NE * s;
}

// ---------------- launch ---------------------------------------------------
extern "C" void kernel_launch(void* const* d_in, const int* in_sizes, int n_in,
                              void* d_out, int out_size) {
    const float* x   = (const float*)d_in[0];
    const float* gw  = (const float*)d_in[1];
    const float* W1  = (const float*)d_in[2];
    const float* b1  = (const float*)d_in[3];
    const float* W2  = (const float*)d_in[4];
    const float* b2  = (const float*)d_in[5];
    float* out = (float*)d_out;

    cudaFuncSetAttribute(gemm_mma<D_IN, D_HID, true>,
                         cudaFuncAttributeMaxDynamicSharedMemorySize, SMEM_BYTES);
    cudaFuncSetAttribute(gemm_mma<D_HID, D_IN, false>,
                         cudaFuncAttributeMaxDynamicSharedMemorySize, SMEM_BYTES);

    bf16 *xh, *xl, *w1h, *w1l, *w2h, *w2l, *hh, *hl;
    cudaGetSymbolAddress((void**)&xh,  g_xh);
    cudaGetSymbolAddress((void**)&xl,  g_xl);
    cudaGetSymbolAddress((void**)&w1h, g_w1h);
    cudaGetSymbolAddress((void**)&w1l, g_w1l);
    cudaGetSymbolAddress((void**)&w2h, g_w2h);
    cudaGetSymbolAddress((void**)&w2l, g_w2l);
    cudaGetSymbolAddress((void**)&hh,  g_hh);
    cudaGetSymbolAddress((void**)&hl,  g_hl);

    int nx  = T_TOK * D_IN / 4;
    int nw1 = NE * D_IN * D_HID / 4;
    int nw2 = NE * D_HID * D_IN / 4;
    split_k<<<(nx  + 255) / 256, 256>>>((const float4*)x,  (bf162*)xh,  (bf162*)xl,  nx);
    split_k<<<(nw1 + 255) / 256, 256>>>((const float4*)W1, (bf162*)w1h, (bf162*)w1l, nw1);
    split_k<<<(nw2 + 255) / 256, 256>>>((const float4*)W2, (bf162*)w2h, (bf162*)w2l, nw2);

    init_k  <<<(T_TOK * D_IN / 4 + 255) / 256, 256>>>((float4*)out);
    router_k<<<T_TOK / 8, 256>>>(x, gw);
    offs_k  <<<1, 1>>>();
    scat_k  <<<T_TOK / 256, 256>>>();

    gemm_mma<D_IN, D_HID, true>
        <<<dim3(D_HID / BN, MTILES), 256, SMEM_BYTES>>>(xh, xl, w1h, w1l, b1, out);
    gemm_mma<D_HID, D_IN, false>
        <<<dim3(D_IN / BN, MTILES), 256, SMEM_BYTES>>>(hh, hl, w2h, w2l, b2, out);

    aux_k   <<<1, 1>>>(out, out_size);
}

// round 10
// speedup vs baseline: 5.4956x; 1.0128x over previous
#include <cuda_runtime.h>
#include <cuda_bf16.h>
#include <math.h>
#include <stdint.h>

#define T_TOK  8192
#define D_IN   1024
#define D_HID  4096
#define NE     8
#define TOPK   2

#define BM 128
#define BN 256
#define BK 32
#define PADM   (T_TOK*TOPK + NE*BM)   /* 17408 */
#define MTILES (PADM/BM)              /* 136 */

#define APAD 40    /* halfs per A smem row (32 data + 8 pad) */
#define BPAD 264   /* halfs per B smem row (256 data + 8 pad) */
#define AH_OFF 0
#define AL_OFF (BM*APAD)                 /* 5120 halfs */
#define BH_OFF (2*BM*APAD)               /* 10240 */
#define BL_OFF (2*BM*APAD + BK*BPAD)     /* 18688 */
#define ST_H   (2*BM*APAD + 2*BK*BPAD)   /* 27136 halfs per stage */
#define NSTG   3
#define SMEM_BYTES (NSTG*ST_H*2)         /* 162816 B */

typedef __nv_bfloat16  bf16;
typedef __nv_bfloat162 bf162;

// ---------------- scratch (static device globals; no allocation) ----------
__device__ __align__(16) bf16 g_xh [(size_t)T_TOK*D_IN];
__device__ __align__(16) bf16 g_xl [(size_t)T_TOK*D_IN];
__device__ __align__(16) bf16 g_w1h[(size_t)NE*D_IN*D_HID];
__device__ __align__(16) bf16 g_w1l[(size_t)NE*D_IN*D_HID];
__device__ __align__(16) bf16 g_w2h[(size_t)NE*D_HID*D_IN];
__device__ __align__(16) bf16 g_w2l[(size_t)NE*D_HID*D_IN];
__device__ __align__(16) bf16 g_hh [(size_t)PADM*D_HID];
__device__ __align__(16) bf16 g_hl [(size_t)PADM*D_HID];
__device__ int   g_sel[T_TOK*TOPK];
__device__ float g_wt [T_TOK*TOPK];
__device__ float g_wtp[PADM];
__device__ float g_prob_sum[NE];
__device__ int   g_count[NE];
__device__ int   g_fill[NE];
__device__ int   g_poff[NE+1];
__device__ int   g_ptot;
__device__ int   g_ptok[PADM];

// ---------------- fp32 -> bf16 hi/lo split ---------------------------------
__global__ void split_k(const float4* __restrict__ in, bf162* __restrict__ h,
                        bf162* __restrict__ l, int n4) {
    int i = blockIdx.x * blockDim.x + threadIdx.x;
    if (i >= n4) return;
    float4 v = in[i];
    bf16 h0 = __float2bfloat16(v.x), h1 = __float2bfloat16(v.y);
    bf16 h2 = __float2bfloat16(v.z), h3 = __float2bfloat16(v.w);
    bf16 l0 = __float2bfloat16(v.x - __bfloat162float(h0));
    bf16 l1 = __float2bfloat16(v.y - __bfloat162float(h1));
    bf16 l2 = __float2bfloat16(v.z - __bfloat162float(h2));
    bf16 l3 = __float2bfloat16(v.w - __bfloat162float(h3));
    bf162 a; a.x = h0; a.y = h1;
    bf162 b; b.x = h2; b.y = h3;
    h[2*i] = a; h[2*i+1] = b;
    a.x = l0; a.y = l1; b.x = l2; b.y = l3;
    l[2*i] = a; l[2*i+1] = b;
}

// ---------------- init: counters, ptok, and zero the output ----------------
__global__ void init_k(float4* __restrict__ out4) {
    int i = blockIdx.x * blockDim.x + threadIdx.x;
    if (i < T_TOK * D_IN / 4) out4[i] = make_float4(0.f, 0.f, 0.f, 0.f);
    if (i < PADM) g_ptok[i] = -1;
    if (i < NE) { g_prob_sum[i] = 0.f; g_count[i] = 0; g_fill[i] = 0; }
}

// ---------------- router: 1 warp per token --------------------------------
__global__ void router_k(const float* __restrict__ x, const float* __restrict__ gw) {
    __shared__ float sg[D_IN * NE];
    __shared__ float s_prob[NE];
    __shared__ int   s_cnt[NE];
    int tid = threadIdx.x;
    for (int i = tid; i < D_IN * NE; i += 256) sg[i] = gw[i];
    if (tid < NE) { s_prob[tid] = 0.f; s_cnt[tid] = 0; }
    __syncthreads();

    int warp = tid >> 5, lane = tid & 31;
    int t = blockIdx.x * 8 + warp;
    const float* xr = x + (size_t)t * D_IN;

    float acc[NE];
#pragma unroll
    for (int e = 0; e < NE; e++) acc[e] = 0.f;
    for (int i = lane; i < D_IN; i += 32) {
        float xv = xr[i];
        const float* g = &sg[i * NE];
#pragma unroll
        for (int e = 0; e < NE; e++) acc[e] += xv * g[e];
    }
#pragma unroll
    for (int e = 0; e < NE; e++)
        for (int o = 16; o; o >>= 1) acc[e] += __shfl_xor_sync(0xffffffffu, acc[e], o);

    if (lane == 0) {
        float mx = acc[0];
#pragma unroll
        for (int e = 1; e < NE; e++) mx = fmaxf(mx, acc[e]);
        float p[NE], s = 0.f;
#pragma unroll
        for (int e = 0; e < NE; e++) { p[e] = expf(acc[e] - mx); s += p[e]; }
        float inv = 1.f / s;
#pragma unroll
        for (int e = 0; e < NE; e++) p[e] *= inv;

        int i1 = 0;
#pragma unroll
        for (int e = 1; e < NE; e++) if (p[e] > p[i1]) i1 = e;
        int i2 = (i1 == 0) ? 1 : 0;
#pragma unroll
        for (int e = 0; e < NE; e++) if (e != i1 && p[e] > p[i2]) i2 = e;

        float d = p[i1] + p[i2] + 1e-6f;
        g_sel[t*2]   = i1;  g_sel[t*2+1] = i2;
        g_wt [t*2]   = p[i1] / d;
        g_wt [t*2+1] = p[i2] / d;
#pragma unroll
        for (int e = 0; e < NE; e++) atomicAdd(&s_prob[e], p[e]);
        atomicAdd(&s_cnt[i1], 1);
        atomicAdd(&s_cnt[i2], 1);
    }
    __syncthreads();
    if (tid < NE) {
        atomicAdd(&g_prob_sum[tid], s_prob[tid]);
        atomicAdd(&g_count[tid], s_cnt[tid]);
    }
}

// ---------------- offsets (tiny) ------------------------------------------
__global__ void offs_k() {
    int off = 0;
    for (int e = 0; e < NE; e++) {
        g_poff[e] = off;
        off += ((g_count[e] + BM - 1) / BM) * BM;
    }
    g_poff[NE] = off;
    g_ptot = off;
}

// ---------------- scatter --------------------------------------------------
__global__ void scat_k() {
    int t = blockIdx.x * blockDim.x + threadIdx.x;
    if (t >= T_TOK) return;
#pragma unroll
    for (int k = 0; k < TOPK; k++) {
        int e = g_sel[t*2 + k];
        int j = atomicAdd(&g_fill[e], 1);
        int pos = g_poff[e] + j;
        g_ptok[pos] = t;
        g_wtp[pos]  = g_wt[t*2 + k];
    }
}

// ---------------- MMA helpers ----------------------------------------------
__device__ __forceinline__ void cpa16(uint32_t dst, const void* src) {
    asm volatile("cp.async.cg.shared.global [%0], [%1], 16;\n" :: "r"(dst), "l"(src));
}
__device__ __forceinline__ void ldmx4(uint32_t* r, uint32_t addr) {
    asm volatile("ldmatrix.sync.aligned.m8n8.x4.shared.b16 {%0,%1,%2,%3}, [%4];\n"
        : "=r"(r[0]), "=r"(r[1]), "=r"(r[2]), "=r"(r[3]) : "r"(addr));
}
__device__ __forceinline__ void ldmx4t(uint32_t* r, uint32_t addr) {
    asm volatile("ldmatrix.sync.aligned.m8n8.x4.trans.shared.b16 {%0,%1,%2,%3}, [%4];\n"
        : "=r"(r[0]), "=r"(r[1]), "=r"(r[2]), "=r"(r[3]) : "r"(addr));
}
__device__ __forceinline__ void mma16816(float* c, const uint32_t* a, const uint32_t* b) {
    asm volatile("mma.sync.aligned.m16n8k16.row.col.f32.bf16.bf16.f32 "
        "{%0,%1,%2,%3}, {%4,%5,%6,%7}, {%8,%9}, {%0,%1,%2,%3};\n"
        : "+f"(c[0]), "+f"(c[1]), "+f"(c[2]), "+f"(c[3])
        : "r"(a[0]), "r"(a[1]), "r"(a[2]), "r"(a[3]), "r"(b[0]), "r"(b[1]));
}
__device__ __forceinline__ float gelu_exact(float v) {
    return 0.5f * v * (1.0f + erff(v * 0.70710678118654752440f));
}

// ---------------- split-precision MMA GEMM (128x256 tile) ------------------
// FIRST=true : A gathered by token, epilogue = bias+GELU -> hi/lo bf16 hidden
// FIRST=false: A = permuted hidden rows, epilogue = (acc+bias)*w atomicAdd out
template<int KD, int ND, bool FIRST>
__global__ void __launch_bounds__(256, 1) gemm_mma(
    const bf16* __restrict__ Ah_g, const bf16* __restrict__ Al_g,
    const bf16* __restrict__ Bh_g, const bf16* __restrict__ Bl_g,
    const float* __restrict__ bias, float* __restrict__ out)
{
    extern __shared__ bf16 smem[];
    __shared__ int   s_tok[BM];
    __shared__ float s_w[BM];

    int row0 = blockIdx.y * BM;
    if (row0 >= g_ptot) return;
    int e = 0;
    while (row0 >= g_poff[e + 1]) e++;
    int n0 = blockIdx.x * BN;

    int tid = threadIdx.x;
    if (tid < BM) {
        int t = g_ptok[row0 + tid];
        s_tok[tid] = t;
        if (!FIRST) s_w[tid] = g_wtp[row0 + tid];
    }
    __syncthreads();

    const bf16* Bh_e = Bh_g + (size_t)e * KD * ND + n0;
    const bf16* Bl_e = Bl_g + (size_t)e * KD * ND + n0;

    uint32_t smem_base = (uint32_t)__cvta_generic_to_shared(smem);

    auto load_stage = [&](int stage, int k0) {
        uint32_t sb = smem_base + (uint32_t)stage * (ST_H * 2);
        // A: 128 rows x 4 chunks(16B) x {h,l} = 1024 cp.async
#pragma unroll
        for (int m = 0; m < 4; m++) {
            int c = tid + m * 256;
            int hl = c & 1, j = (c >> 1) & 3, r = c >> 3;
            int tk = s_tok[r];
            size_t arow = FIRST ? (size_t)(tk < 0 ? 0 : tk) * KD : (size_t)(row0 + r) * KD;
            uint32_t offA = (uint32_t)(r * APAD + j * 8) * 2;
            cpa16(sb + (hl ? AL_OFF : AH_OFF) * 2 + offA,
                  (hl ? Al_g : Ah_g) + arow + k0 + j * 8);
        }
        // B: 32 rows x 32 chunks(16B) x {h,l} = 2048 cp.async
#pragma unroll
        for (int m = 0; m < 8; m++) {
            int c = tid + m * 256;
            int hl = c & 1, jb = (c >> 1) & 31, rb = c >> 6;
            size_t brow = (size_t)(k0 + rb) * ND + jb * 8;
            uint32_t offB = (uint32_t)(rb * BPAD + jb * 8) * 2;
            cpa16(sb + (hl ? BL_OFF : BH_OFF) * 2 + offB, (hl ? Bl_e : Bh_e) + brow);
        }
    };

    int lane = tid & 31, warp = tid >> 5;
    int wm = (warp >> 2) * 64;   // 2 warp-rows x 64
    int wn = (warp & 3) * 64;    // 4 warp-cols x 64
    uint32_t rowSel = (lane & 7) + ((lane >> 3) & 1) * 8;
    uint32_t colSel = (lane >> 4) * 8;

    float acc[4][8][4];
#pragma unroll
    for (int i = 0; i < 4; i++)
#pragma unroll
        for (int j = 0; j < 8; j++)
#pragma unroll
            for (int q = 0; q < 4; q++) acc[i][j][q] = 0.f;

    auto compute = [&](int stage) {
        uint32_t sb = smem_base + (uint32_t)stage * (ST_H * 2);
        uint32_t ah = sb + AH_OFF * 2, al = sb + AL_OFF * 2;
        uint32_t bh = sb + BH_OFF * 2, bl = sb + BL_OFF * 2;
#pragma unroll
        for (int kk = 0; kk < 2; kk++) {
            int k16 = kk * 16;
            uint32_t bhF[4][4], blF[4][4];
#pragma unroll
            for (int nj = 0; nj < 4; nj++) {
                uint32_t off = (uint32_t)((k16 + rowSel) * BPAD + wn + nj * 16 + colSel) * 2;
                ldmx4t(bhF[nj], bh + off);
                ldmx4t(blF[nj], bl + off);
            }
            uint32_t aF[4][4];
#pragma unroll
            for (int mi = 0; mi < 4; mi++) {
                uint32_t off = (uint32_t)((wm + mi * 16 + rowSel) * APAD + k16 + colSel) * 2;
                ldmx4(aF[mi], ah + off);
            }
#pragma unroll
            for (int mi = 0; mi < 4; mi++)
#pragma unroll
                for (int ni = 0; ni < 8; ni++) {
                    mma16816(acc[mi][ni], aF[mi], &bhF[ni >> 1][(ni & 1) * 2]);
                    mma16816(acc[mi][ni], aF[mi], &blF[ni >> 1][(ni & 1) * 2]);
                }
#pragma unroll
            for (int mi = 0; mi < 4; mi++) {
                uint32_t off = (uint32_t)((wm + mi * 16 + rowSel) * APAD + k16 + colSel) * 2;
                ldmx4(aF[mi], al + off);
            }
#pragma unroll
            for (int mi = 0; mi < 4; mi++)
#pragma unroll
                for (int ni = 0; ni < 8; ni++)
                    mma16816(acc[mi][ni], aF[mi], &bhF[ni >> 1][(ni & 1) * 2]);
        }
    };

    const int NIT = KD / BK;
    load_stage(0, 0);
    asm volatile("cp.async.commit_group;\n");
    load_stage(1, BK);
    asm volatile("cp.async.commit_group;\n");

#pragma unroll 1
    for (int it = 0; it < NIT; ++it) {
        asm volatile("cp.async.wait_group 1;\n");
        __syncthreads();
        int s = it % NSTG;
        compute(s);
        if (it + 2 < NIT) {
            int s2 = (it + 2) % NSTG;
            load_stage(s2, (it + 2) * BK);
        }
        asm volatile("cp.async.commit_group;\n");   // always: uniform group count
    }

    int g = lane >> 2, tg = lane & 3;
#pragma unroll
    for (int mi = 0; mi < 4; mi++)
#pragma unroll
        for (int ni = 0; ni < 8; ni++)
#pragma unroll
            for (int h = 0; h < 2; h++) {
                int m = wm + mi * 16 + g + h * 8;
                int n = n0 + wn + ni * 8 + 2 * tg;
                float v0 = acc[mi][ni][h * 2 + 0] + bias[e * ND + n];
                float v1 = acc[mi][ni][h * 2 + 1] + bias[e * ND + n + 1];
                if (FIRST) {
                    if (s_tok[m] < 0) continue;
                    size_t orow = (size_t)(row0 + m) * ND + n;
                    v0 = gelu_exact(v0);
                    v1 = gelu_exact(v1);
                    bf16 h0 = __float2bfloat16(v0), h1 = __float2bfloat16(v1);
                    bf16 l0 = __float2bfloat16(v0 - __bfloat162float(h0));
                    bf16 l1 = __float2bfloat16(v1 - __bfloat162float(h1));
                    bf162 ph; ph.x = h0; ph.y = h1;
                    bf162 pl; pl.x = l0; pl.y = l1;
                    *(bf162*)&g_hh[orow] = ph;
                    *(bf162*)&g_hl[orow] = pl;
                } else {
                    int tok = s_tok[m];
                    if (tok < 0) continue;
                    float w = s_w[m];
                    atomicAdd(&out[(size_t)tok * ND + n],     v0 * w);
                    atomicAdd(&out[(size_t)tok * ND + n + 1], v1 * w);
                }
            }
}

// ---------------- aux loss -------------------------------------------------
__global__ void aux_k(float* __restrict__ out, int out_size) {
    if (out_size <= T_TOK * D_IN) return;
    float s = 0.f;
    for (int e = 0; e < NE; e++) {
        float mean_prob = g_prob_sum[e] / (float)T_TOK;
        float frac = (float)g_count[e] / (float)(T_TOK * TOPK);
        s += mean_prob * frac;
    }
    out[T_TOK * D_IN] = (float)NE * s;
}

// ---------------- launch ---------------------------------------------------
extern "C" void kernel_launch(void* const* d_in, const int* in_sizes, int n_in,
                              void* d_out, int out_size) {
    const float* x   = (const float*)d_in[0];
    const float* gw  = (const float*)d_in[1];
    const float* W1  = (const float*)d_in[2];
    const float* b1  = (const float*)d_in[3];
    const float* W2  = (const float*)d_in[4];
    const float* b2  = (const float*)d_in[5];
    float* out = (float*)d_out;

    cudaFuncSetAttribute(gemm_mma<D_IN, D_HID, true>,
                         cudaFuncAttributeMaxDynamicSharedMemorySize, SMEM_BYTES);
    cudaFuncSetAttribute(gemm_mma<D_HID, D_IN, false>,
                         cudaFuncAttributeMaxDynamicSharedMemorySize, SMEM_BYTES);

    bf16 *xh, *xl, *w1h, *w1l, *w2h, *w2l, *hh, *hl;
    cudaGetSymbolAddress((void**)&xh,  g_xh);
    cudaGetSymbolAddress((void**)&xl,  g_xl);
    cudaGetSymbolAddress((void**)&w1h, g_w1h);
    cudaGetSymbolAddress((void**)&w1l, g_w1l);
    cudaGetSymbolAddress((void**)&w2h, g_w2h);
    cudaGetSymbolAddress((void**)&w2l, g_w2l);
    cudaGetSymbolAddress((void**)&hh,  g_hh);
    cudaGetSymbolAddress((void**)&hl,  g_hl);

    int nx  = T_TOK * D_IN / 4;
    int nw1 = NE * D_IN * D_HID / 4;
    int nw2 = NE * D_HID * D_IN / 4;
    split_k<<<(nx  + 255) / 256, 256>>>((const float4*)x,  (bf162*)xh,  (bf162*)xl,  nx);
    split_k<<<(nw1 + 255) / 256, 256>>>((const float4*)W1, (bf162*)w1h, (bf162*)w1l, nw1);
    split_k<<<(nw2 + 255) / 256, 256>>>((const float4*)W2, (bf162*)w2h, (bf162*)w2l, nw2);

    init_k  <<<(T_TOK * D_IN / 4 + 255) / 256, 256>>>((float4*)out);
    router_k<<<T_TOK / 8, 256>>>(x, gw);
    offs_k  <<<1, 1>>>();
    scat_k  <<<T_TOK / 256, 256>>>();

    gemm_mma<D_IN, D_HID, true>
        <<<dim3(D_HID / BN, MTILES), 256, SMEM_BYTES>>>(xh, xl, w1h, w1l, b1, out);
    gemm_mma<D_HID, D_IN, false>
        <<<dim3(D_IN / BN, MTILES), 256, SMEM_BYTES>>>(hh, hl, w2h, w2l, b2, out);

    aux_k   <<<1, 1>>>(out, out_size);
}